// round 1
// baseline (speedup 1.0000x reference)
#include <cuda_runtime.h>

// Problem constants
#define M_MATCH 5000
#define TOT     10000      // 2*M
#define CF      128
#define CC      256
#define WW      25
#define LCELLS  4800
#define HFD     240
#define WFD     320

// scratch: t[m][o] = c_win[m] @ W2^T + merge_b  (5.12 MB)
__device__ float g_t[TOT * CF];

// ---------------------------------------------------------------------------
// Kernel A: coarse down-projection + second-half merge contribution
//   c_win = feat_c[b,l] @ Wd^T + bd      (256 -> 128)
//   t     = c_win @ W2^T + bm            (128 -> 128),  W2 = merge_w[:,128:]
// 128 threads/block (thread = output channel o), weights cached in smem with
// pitch chosen so per-thread float4 row reads are bank-conflict-free
// (pitch*4 mod 128 == 16 -> 8 distinct 16B banksets per LDS.128 phase).
// ---------------------------------------------------------------------------
__global__ void __launch_bounds__(128, 1)
proj_kernel(const float* __restrict__ feat_c0, const float* __restrict__ feat_c1,
            const int* __restrict__ b_ids, const int* __restrict__ i_ids,
            const int* __restrict__ j_ids,
            const float* __restrict__ Wd, const float* __restrict__ bd,
            const float* __restrict__ Wm, const float* __restrict__ bm)
{
    extern __shared__ float sm[];
    float* Wd_s  = sm;                      // 128 x 260 (pitch 260)
    float* W2_s  = sm + 128 * 260;          // 128 x 132 (pitch 132)
    float* cfeat = W2_s + 128 * 132;        // 256
    float* cwin  = cfeat + 256;             // 128

    const int tid = threadIdx.x;

    for (int idx = tid; idx < 128 * 256; idx += 128) {
        int o = idx >> 8, c = idx & 255;
        Wd_s[o * 260 + c] = Wd[idx];
    }
    for (int idx = tid; idx < 128 * 128; idx += 128) {
        int o = idx >> 7, c = idx & 127;
        W2_s[o * 132 + c] = Wm[o * 256 + 128 + c];
    }
    const float bdo = bd[tid];
    const float bmo = bm[tid];
    __syncthreads();

    const float* wrow  = Wd_s + tid * 260;
    const float* w2row = W2_s + tid * 132;

    for (int m = blockIdx.x; m < TOT; m += gridDim.x) {
        const int  mm = (m < M_MATCH) ? m : m - M_MATCH;
        const int  b  = b_ids[mm];
        const int  l  = (m < M_MATCH) ? i_ids[mm] : j_ids[mm];
        const float* src = ((m < M_MATCH) ? feat_c0 : feat_c1)
                         + ((long)b * LCELLS + l) * CC;

        cfeat[tid]       = src[tid];
        cfeat[tid + 128] = src[tid + 128];
        __syncthreads();

        float a0 = 0.f, a1 = 0.f, a2 = 0.f, a3 = 0.f;
        #pragma unroll 8
        for (int c = 0; c < 256; c += 4) {
            float4 wv = *(const float4*)(wrow + c);
            float4 cv = *(const float4*)(cfeat + c);
            a0 += wv.x * cv.x; a1 += wv.y * cv.y;
            a2 += wv.z * cv.z; a3 += wv.w * cv.w;
        }
        cwin[tid] = (a0 + a1) + (a2 + a3) + bdo;
        __syncthreads();

        float b0 = 0.f, b1 = 0.f, b2 = 0.f, b3 = 0.f;
        #pragma unroll 8
        for (int c = 0; c < 128; c += 4) {
            float4 wv = *(const float4*)(w2row + c);
            float4 cv = *(const float4*)(cwin + c);
            b0 += wv.x * cv.x; b1 += wv.y * cv.y;
            b2 += wv.z * cv.z; b3 += wv.w * cv.w;
        }
        g_t[(long)m * CF + tid] = (b0 + b1) + (b2 + b3) + bmo;
        __syncthreads();   // protect cfeat/cwin before next row overwrites
    }
}

// ---------------------------------------------------------------------------
// Kernel B: per-match gather of the viewed-unfold window + [25,128]@[128,128]
// merge GEMM, t added as accumulator init.
// f[m,w,c] = unfold element at flat = l*3200 + w*128 + c:
//   ch = flat/120000, k = (flat/4800)%25, pos = flat%4800
//   row = (pos/80)*4 + k/5 - 2, col = (pos%80)*4 + k%5 - 2   (zero OOB)
// 256 threads: o-tile of 4 (tid&31 -> o0=4*og), w-tile of 4 (wg = tid>>5,
// w = wg + 8j; w>=25 lanes compute garbage but never store).
// 4x4 register tile => 64 FMA per 8 LDS.128 (at the 128B/cyc smem ceiling).
// ---------------------------------------------------------------------------
__global__ void __launch_bounds__(256, 2)
fine_kernel(const float* __restrict__ feat_f0, const float* __restrict__ feat_f1,
            const int* __restrict__ b_ids, const int* __restrict__ i_ids,
            const int* __restrict__ j_ids,
            const float* __restrict__ Wm, float* __restrict__ out)
{
    extern __shared__ float sm[];
    float* W1T = sm;               // [c][o] 128x128 = 64KB
    float* fsm = sm + 128 * 128;   // 32 x 128 = 16KB (rows 25..31 are dont-care)

    const int tid = threadIdx.x;

    for (int idx = tid; idx < 128 * 128; idx += 256) {
        int o = idx >> 7, c = idx & 127;
        W1T[c * 128 + o] = Wm[o * 256 + c];    // W1 = merge_w[:, :128]
    }

    const int og = tid & 31;
    const int o0 = og * 4;
    const int wg = tid >> 5;       // 0..7
    __syncthreads();

    for (int m = blockIdx.x; m < TOT; m += gridDim.x) {
        const int mm = (m < M_MATCH) ? m : m - M_MATCH;
        const int b  = b_ids[mm];
        const int l  = (m < M_MATCH) ? i_ids[mm] : j_ids[mm];
        const float* fb = ((m < M_MATCH) ? feat_f0 : feat_f1)
                        + (long)b * (CF * HFD * WFD);

        // ---- gather window tile into smem ----
        const unsigned base = (unsigned)l * 3200u;
        #pragma unroll
        for (int it = 0; it < 13; it++) {
            int e = tid + it * 256;
            if (e < 3200) {
                unsigned flat = base + (unsigned)e;
                unsigned ch  = flat / 120000u;
                unsigned r1  = flat - ch * 120000u;
                unsigned k   = r1 / 4800u;
                unsigned pos = r1 - k * 4800u;
                int kh = (int)(k / 5u), kw = (int)(k - 5u * (k / 5u));
                int oh = (int)(pos / 80u), ow = (int)(pos - 80u * (pos / 80u));
                int row = oh * 4 + kh - 2;
                int col = ow * 4 + kw - 2;
                float v = 0.f;
                if ((unsigned)row < (unsigned)HFD && (unsigned)col < (unsigned)WFD)
                    v = __ldg(fb + ((long)ch * HFD + row) * WFD + col);
                fsm[e] = v;
            }
        }
        __syncthreads();

        // ---- accumulator init from t (broadcast over w) ----
        const float4 t4 = *(const float4*)(&g_t[(long)m * CF + o0]);
        float acc[4][4];
        #pragma unroll
        for (int j = 0; j < 4; j++) {
            acc[j][0] = t4.x; acc[j][1] = t4.y;
            acc[j][2] = t4.z; acc[j][3] = t4.w;
        }

        // ---- 4x4 register-tiled GEMM over c ----
        #pragma unroll 4
        for (int c = 0; c < 128; c += 4) {
            const float4 w0 = *(const float4*)(&W1T[(c + 0) * 128 + o0]);
            const float4 w1 = *(const float4*)(&W1T[(c + 1) * 128 + o0]);
            const float4 w2 = *(const float4*)(&W1T[(c + 2) * 128 + o0]);
            const float4 w3 = *(const float4*)(&W1T[(c + 3) * 128 + o0]);
            #pragma unroll
            for (int j = 0; j < 4; j++) {
                const float4 fv = *(const float4*)(&fsm[(wg + 8 * j) * 128 + c]);
                acc[j][0] += fv.x * w0.x + fv.y * w1.x + fv.z * w2.x + fv.w * w3.x;
                acc[j][1] += fv.x * w0.y + fv.y * w1.y + fv.z * w2.y + fv.w * w3.y;
                acc[j][2] += fv.x * w0.z + fv.y * w1.z + fv.z * w2.z + fv.w * w3.z;
                acc[j][3] += fv.x * w0.w + fv.y * w1.w + fv.z * w2.w + fv.w * w3.w;
            }
        }

        // ---- store (guard w < 25) ----
        #pragma unroll
        for (int j = 0; j < 4; j++) {
            int w = wg + 8 * j;
            if (w < WW) {
                float4 r = make_float4(acc[j][0], acc[j][1], acc[j][2], acc[j][3]);
                *(float4*)(&out[(long)m * 3200 + w * 128 + o0]) = r;
            }
        }
        __syncthreads();   // fsm reused next match
    }
}

// ---------------------------------------------------------------------------
extern "C" void kernel_launch(void* const* d_in, const int* in_sizes, int n_in,
                              void* d_out, int out_size)
{
    (void)in_sizes; (void)n_in; (void)out_size;
    const float* feat_f0 = (const float*)d_in[0];
    const float* feat_f1 = (const float*)d_in[1];
    const float* feat_c0 = (const float*)d_in[2];
    const float* feat_c1 = (const float*)d_in[3];
    const int*   b_ids   = (const int*)d_in[4];
    const int*   i_ids   = (const int*)d_in[5];
    const int*   j_ids   = (const int*)d_in[6];
    const float* Wd      = (const float*)d_in[7];
    const float* bd      = (const float*)d_in[8];
    const float* Wm      = (const float*)d_in[9];
    const float* bm      = (const float*)d_in[10];
    float* out = (float*)d_out;

    const size_t smemA = (size_t)(128 * 260 + 128 * 132 + 256 + 128) * sizeof(float);
    const size_t smemB = (size_t)(128 * 128 + 32 * 128) * sizeof(float);
    cudaFuncSetAttribute(proj_kernel, cudaFuncAttributeMaxDynamicSharedMemorySize, (int)smemA);
    cudaFuncSetAttribute(fine_kernel, cudaFuncAttributeMaxDynamicSharedMemorySize, (int)smemB);

    proj_kernel<<<148, 128, smemA>>>(feat_c0, feat_c1, b_ids, i_ids, j_ids,
                                     Wd, bd, Wm, bm);
    fine_kernel<<<296, 256, smemB>>>(feat_f0, feat_f1, b_ids, i_ids, j_ids,
                                     Wm, out);
}